// round 3
// baseline (speedup 1.0000x reference)
#include <cuda_runtime.h>
#include <cstdint>
#include <cstddef>

// Harness PTX target is base sm_103 — no tcgen05. Tensor path: mma.sync tf32.
// tf32 RNA rounding hoisted to a pre-pass into __device__ scratch; mainloop is cvt-free.

// ---------------- problem constants ----------------
#define N_TOK   16384
#define F_DIM   1024
#define B_DIM   512
#define TILE_M  128
#define TILE_F  64
#define GCOLS   256          // 4 gates * TILE_F
#define KC      32           // K per chunk (128B rows)
#define NCHUNK  48
#define THREADS 256
#define STAGES  4

// ---------------- smem layout ----------------
#define ABYTES      (TILE_M * KC * 4)          // 16384
#define BBYTES      (GCOLS * KC * 4)           // 32768
#define STAGE_BYTES (ABYTES + BBYTES)          // 49152
#define GSM_PITCH   68
#define GSM_BYTES   (4 * 128 * GSM_PITCH * 4)  // 139264 (epilogue, unions stages)
#define SM_BIAS     (STAGES * STAGE_BYTES)     // 196608
#define SMEM_TOTAL  (SM_BIAS + 256 * 4)        // 197632

static_assert(GSM_BYTES <= STAGES * STAGE_BYTES, "epilogue union");
static_assert(SMEM_TOTAL <= 227 * 1024, "smem cap");

// ---------------- tf32-rounded scratch (device globals are the allowed scratch) ----
__device__ float g_h [N_TOK * F_DIM];     // 64 MB
__device__ float g_x [N_TOK * B_DIM];     // 32 MB
__device__ float g_wh[4 * F_DIM * F_DIM]; // 16 MB
__device__ float g_wx[4 * F_DIM * B_DIM]; //  8 MB

// ---------------- helpers ----------------
static __device__ __forceinline__ uint32_t smem_u32(const void* p) {
    uint32_t a;
    asm("{ .reg .u64 t; cvta.to.shared.u64 t, %1; cvt.u32.u64 %0, t; }" : "=r"(a) : "l"(p));
    return a;
}

static __device__ __forceinline__ void cp16(uint32_t dst, const void* src) {
    asm volatile("cp.async.cg.shared.global [%0], [%1], 16;" :: "r"(dst), "l"(src) : "memory");
}

static __device__ __forceinline__ float rna_tf32(float f) {
    uint32_t r;
    asm("cvt.rna.tf32.f32 %0, %1;" : "=r"(r) : "f"(f));
    return __uint_as_float(r);
}

static __device__ __forceinline__ void mma_tf32(float* c, const uint32_t* a, const uint32_t* b) {
    asm volatile(
        "mma.sync.aligned.m16n8k8.row.col.f32.tf32.tf32.f32 "
        "{%0,%1,%2,%3}, {%4,%5,%6,%7}, {%8,%9}, {%0,%1,%2,%3};"
        : "+f"(c[0]), "+f"(c[1]), "+f"(c[2]), "+f"(c[3])
        : "r"(a[0]), "r"(a[1]), "r"(a[2]), "r"(a[3]), "r"(b[0]), "r"(b[1]));
}

static __device__ __forceinline__ float sigf(float x) { return 1.0f / (1.0f + __expf(-x)); }
static __device__ __forceinline__ float tanh_fast(float x) {
    return 2.0f / (1.0f + __expf(-2.0f * x)) - 1.0f;
}

// ---------------- pre-pass: RNA-round fp32 -> tf32-in-fp32 ----------------
__global__ void __launch_bounds__(256) preround_kernel(const float4* __restrict__ src,
                                                       float4* __restrict__ dst, int n4) {
    int i = blockIdx.x * 256 + threadIdx.x;
    if (i < n4) {
        float4 v = src[i];
        v.x = rna_tf32(v.x); v.y = rna_tf32(v.y);
        v.z = rna_tf32(v.z); v.w = rna_tf32(v.w);
        dst[i] = v;
    }
}

// ---------------- mainloop chunk loader ----------------
static __device__ __forceinline__ void issue_chunk(int chunk, uint32_t sb, int tid,
                                                   int m_base, int c_base) {
    const float *asrc, *wk;
    int ld;
    if (chunk < 32) {                 // K in [0,1024): h_prev @ Wh^T
        asrc = g_h + (size_t)m_base * F_DIM + chunk * KC;
        wk   = g_wh + chunk * KC;
        ld   = F_DIM;
    } else {                          // K in [1024,1536): behavior @ Wx^T
        asrc = g_x + (size_t)m_base * B_DIM + (chunk - 32) * KC;
        wk   = g_wx + (chunk - 32) * KC;
        ld   = B_DIM;
    }

    const uint32_t abase = sb + (uint32_t)(chunk & (STAGES - 1)) * STAGE_BYTES;
#pragma unroll
    for (int i = 0; i < 4; ++i) {     // A: 128 rows x 128B, SW128
        int idx = tid + i * THREADS;
        int row = idx >> 3, u = idx & 7;
        cp16(abase + row * 128 + (uint32_t)((u ^ (row & 7)) << 4),
             asrc + (size_t)row * ld + u * 4);
    }
    const uint32_t bbase = abase + ABYTES;
#pragma unroll
    for (int i = 0; i < 8; ++i) {     // B: 256 gemm-col rows x 128B, SW128
        int idx = tid + i * THREADS;
        int rr = idx >> 3, u = idx & 7;
        int g = rr >> 6, r = rr & 63;
        cp16(bbase + rr * 128 + (uint32_t)((u ^ (rr & 7)) << 4),
             wk + (size_t)(g * F_DIM + c_base + r) * ld + u * 4);
    }
    asm volatile("cp.async.commit_group;" ::: "memory");
}

__global__ void __launch_bounds__(THREADS, 1)
lstm_mma_kernel(float* __restrict__ out,
                const float* __restrict__ c_prev,
                const float* __restrict__ bias) {
    extern __shared__ char smem[];
    const uint32_t sb = smem_u32(smem);
    const int tid = threadIdx.x;
    const int lane = tid & 31;
    const int wid = tid >> 5;
    const int warp_m = wid & 1;
    const int warp_n = wid >> 1;
    const int la = lane >> 2;
    const int lk = lane & 3;

    const int f_tile = blockIdx.x & 15;
    const int m_tile = blockIdx.x >> 4;
    const int m_base = m_tile * TILE_M;
    const int c_base = f_tile * TILE_F;

    float* bias_s = reinterpret_cast<float*>(smem + SM_BIAS);
    bias_s[tid] = bias[(tid >> 6) * F_DIM + c_base + (tid & 63)];

    float acc[4][8][4];
#pragma unroll
    for (int mt = 0; mt < 4; ++mt)
#pragma unroll
        for (int nt = 0; nt < 8; ++nt)
#pragma unroll
            for (int j = 0; j < 4; ++j) acc[mt][nt][j] = 0.0f;

    // prologue: fill STAGES-1 buffers
#pragma unroll
    for (int p = 0; p < STAGES - 1; ++p)
        issue_chunk(p, sb, tid, m_base, c_base);

    for (int ch = 0; ch < NCHUNK; ++ch) {
        // ensure chunk ch landed (handle pipeline tail counts)
        if (ch < NCHUNK - 2) {
            asm volatile("cp.async.wait_group 2;" ::: "memory");
        } else if (ch == NCHUNK - 2) {
            asm volatile("cp.async.wait_group 1;" ::: "memory");
        } else {
            asm volatile("cp.async.wait_group 0;" ::: "memory");
        }
        __syncthreads();   // also guards reuse of stage (ch-1)%STAGES below

        if (ch + STAGES - 1 < NCHUNK)
            issue_chunk(ch + STAGES - 1, sb, tid, m_base, c_base);

        const char* abase = smem + (size_t)(ch & (STAGES - 1)) * STAGE_BYTES;
        const char* bbase = abase + ABYTES;

#pragma unroll
        for (int ks = 0; ks < 4; ++ks) {
            uint32_t af[4][4];
#pragma unroll
            for (int mt = 0; mt < 4; ++mt) {
                const int r1 = warp_m * 64 + mt * 16 + la;
                const int r2 = r1 + 8;
                af[mt][0] = *(const uint32_t*)(abase + r1 * 128 + (((2 * ks + 0) ^ (r1 & 7)) << 4) + lk * 4);
                af[mt][1] = *(const uint32_t*)(abase + r2 * 128 + (((2 * ks + 0) ^ (r2 & 7)) << 4) + lk * 4);
                af[mt][2] = *(const uint32_t*)(abase + r1 * 128 + (((2 * ks + 1) ^ (r1 & 7)) << 4) + lk * 4);
                af[mt][3] = *(const uint32_t*)(abase + r2 * 128 + (((2 * ks + 1) ^ (r2 & 7)) << 4) + lk * 4);
            }
            uint32_t bf[8][2];
#pragma unroll
            for (int nt = 0; nt < 8; ++nt) {
                const int rn = warp_n * 64 + nt * 8 + la;
                bf[nt][0] = *(const uint32_t*)(bbase + rn * 128 + (((2 * ks + 0) ^ (rn & 7)) << 4) + lk * 4);
                bf[nt][1] = *(const uint32_t*)(bbase + rn * 128 + (((2 * ks + 1) ^ (rn & 7)) << 4) + lk * 4);
            }
#pragma unroll
            for (int mt = 0; mt < 4; ++mt)
#pragma unroll
                for (int nt = 0; nt < 8; ++nt)
                    mma_tf32(acc[mt][nt], af[mt], bf[nt]);
        }
    }
    __syncthreads();   // stage buffers -> epilogue union

    // ---- epilogue: dump 4 gate tiles (128 x 64 each) to smem ----
    float* gsm = reinterpret_cast<float*>(smem);
#pragma unroll
    for (int mt = 0; mt < 4; ++mt) {
#pragma unroll
        for (int nt = 0; nt < 8; ++nt) {
            const int r0 = warp_m * 64 + mt * 16 + la;
            const int f0 = nt * 8 + 2 * lk;
            const size_t o = ((size_t)(warp_n * 128 + r0)) * GSM_PITCH + f0;
            gsm[o]     = acc[mt][nt][0];
            gsm[o + 1] = acc[mt][nt][1];
            gsm[o + 8 * GSM_PITCH]     = acc[mt][nt][2];
            gsm[o + 8 * GSM_PITCH + 1] = acc[mt][nt][3];
        }
    }
    __syncthreads();

    // ---- gate math + coalesced global I/O ----
    const float* cpg = c_prev + (size_t)m_base * F_DIM + c_base;
    float* og = out + (size_t)m_base * F_DIM + c_base;
#pragma unroll
    for (int i = 0; i < (TILE_M * TILE_F) / THREADS; ++i) {
        const int idx = tid + i * THREADS;
        const int row = idx >> 6;
        const int f = idx & 63;
        const float xi = gsm[((size_t)(0 * 128 + row)) * GSM_PITCH + f] + bias_s[f];
        const float xf = gsm[((size_t)(1 * 128 + row)) * GSM_PITCH + f] + bias_s[64 + f];
        const float xg = gsm[((size_t)(2 * 128 + row)) * GSM_PITCH + f] + bias_s[128 + f];
        const float xo = gsm[((size_t)(3 * 128 + row)) * GSM_PITCH + f] + bias_s[192 + f];
        const float cv = sigf(xf) * cpg[(size_t)row * F_DIM + f] + sigf(xi) * tanh_fast(xg);
        og[(size_t)row * F_DIM + f] = sigf(xo) * tanh_fast(cv);
    }
}

extern "C" void kernel_launch(void* const* d_in, const int* in_sizes, int n_in,
                              void* d_out, int out_size) {
    const float* behavior = (const float*)d_in[0];
    const float* h_prev   = (const float*)d_in[1];
    const float* c_prev   = (const float*)d_in[2];
    const float* Wh       = (const float*)d_in[3];
    const float* Wx       = (const float*)d_in[4];
    const float* bias     = (const float*)d_in[5];

    float *p_h, *p_x, *p_wh, *p_wx;
    cudaGetSymbolAddress((void**)&p_h,  g_h);
    cudaGetSymbolAddress((void**)&p_x,  g_x);
    cudaGetSymbolAddress((void**)&p_wh, g_wh);
    cudaGetSymbolAddress((void**)&p_wx, g_wx);

    // pre-pass: RNA-round inputs to tf32-in-fp32 scratch
    auto pr = [&](const float* s, float* d, int n) {
        int n4 = n / 4;
        preround_kernel<<<(n4 + 255) / 256, 256>>>((const float4*)s, (float4*)d, n4);
    };
    pr(h_prev,   p_h,  N_TOK * F_DIM);
    pr(behavior, p_x,  N_TOK * B_DIM);
    pr(Wh,       p_wh, 4 * F_DIM * F_DIM);
    pr(Wx,       p_wx, 4 * F_DIM * B_DIM);

    cudaFuncSetAttribute(lstm_mma_kernel,
                         cudaFuncAttributeMaxDynamicSharedMemorySize, SMEM_TOTAL);

    const int grid = (N_TOK / TILE_M) * (F_DIM / TILE_F);  // 2048
    lstm_mma_kernel<<<grid, THREADS, SMEM_TOTAL>>>((float*)d_out, c_prev, bias);
}